// round 1
// baseline (speedup 1.0000x reference)
#include <cuda_runtime.h>

// ConvSTFT: out[b,k,f,c] = sum_n x_padded[b, f*HOP + n] * basis[k + c*513, n]
// Reformulated as 32 batched GEMMs: C[f,kb] = framed[f,:] . basis[kb,:]
// framed[f,n] = x[f*320 + n - 512] (zero outside [0,160000))
// basis rows are zero outside n in [112, 912)  -> K_eff = 800.

#define T_LEN      160000
#define FRAMES     501
#define NBINS      513
#define BINS_TOT   1026
#define NFFT       1024
#define HOP        320
#define N0         112      // first nonzero basis column
#define KTOT       800      // effective reduction length
#define BK         16
#define BM         64       // frames per block tile
#define BN         64       // bins per block tile
#define NT         (KTOT / BK)   // 50 k-tiles

__global__ __launch_bounds__(256)
void stft_gemm_kernel(const float* __restrict__ x,
                      const float* __restrict__ basis,
                      float* __restrict__ out)
{
    __shared__ __align__(16) float As[BK][BM + 4];   // [n][frame], padded
    __shared__ __align__(16) float Bs[BK][BN + 4];   // [n][bin],   padded

    const int tid  = threadIdx.x;
    const int f0   = blockIdx.x * BM;
    const int k0   = blockIdx.y * BN;
    const int b    = blockIdx.z;

    // Loader mapping: warp covers 16 consecutive columns (n) x 2 rows -> coalesced
    const int colL = tid & 15;    // n within k-tile
    const int rowL = tid >> 4;    // frame / bin row base (stride 16, 4 passes)

    // Compute mapping: 4x4 register tile
    const int tx = tid & 15;      // frame group: m0 = 4*tx
    const int ty = tid >> 4;      // bin group:   n0 = 4*ty
    const int m0 = tx * 4;
    const int nb0 = ty * 4;

    const float* xb = x + (size_t)b * T_LEN;

    // Staging registers for software pipeline
    float aR[4], bR[4];

    auto loadT = [&](int t) {
        const int kk = N0 + t * BK;
#pragma unroll
        for (int i = 0; i < 4; i++) {
            const int m = rowL + 16 * i;
            const int xi = (f0 + m) * HOP + (kk + colL) - 512;
            aR[i] = (xi >= 0 && xi < T_LEN) ? xb[xi] : 0.0f;
            const int kb = k0 + m;
            bR[i] = (kb < BINS_TOT) ? basis[(size_t)kb * NFFT + (kk + colL)] : 0.0f;
        }
    };

    // Packed f32x2 accumulators: acc[j] holds (frame m0+0,m0+1) and (m0+2,m0+3)
    unsigned long long acc[4][2];
#pragma unroll
    for (int j = 0; j < 4; j++) { acc[j][0] = 0ULL; acc[j][1] = 0ULL; }

    loadT(0);

    for (int t = 0; t < NT; t++) {
        __syncthreads();
#pragma unroll
        for (int i = 0; i < 4; i++) {
            const int m = rowL + 16 * i;
            As[colL][m] = aR[i];
            Bs[colL][m] = bR[i];
        }
        __syncthreads();

        if (t + 1 < NT) loadT(t + 1);   // prefetch next tile while computing

#pragma unroll
        for (int k = 0; k < BK; k++) {
            const float4 a  = *(const float4*)&As[k][m0];
            const float4 bv = *(const float4*)&Bs[k][nb0];

            unsigned long long a01, a23;
            asm("mov.b64 %0, {%1,%2};" : "=l"(a01) : "f"(a.x), "f"(a.y));
            asm("mov.b64 %0, {%1,%2};" : "=l"(a23) : "f"(a.z), "f"(a.w));

            const float bj[4] = {bv.x, bv.y, bv.z, bv.w};
#pragma unroll
            for (int j = 0; j < 4; j++) {
                unsigned long long bb;
                asm("mov.b64 %0, {%1,%1};" : "=l"(bb) : "f"(bj[j]));
                asm("fma.rn.f32x2 %0, %1, %2, %0;"
                    : "+l"(acc[j][0]) : "l"(a01), "l"(bb));
                asm("fma.rn.f32x2 %0, %1, %2, %0;"
                    : "+l"(acc[j][1]) : "l"(a23), "l"(bb));
            }
        }
    }

    // Epilogue: unpack and scatter to out[b, k, f, comp]
#pragma unroll
    for (int j = 0; j < 4; j++) {
        const int kb = k0 + nb0 + j;
        if (kb >= BINS_TOT) continue;
        int kout, comp;
        if (kb < NBINS) { kout = kb;         comp = 0; }
        else            { kout = kb - NBINS; comp = 1; }
        const size_t base = (((size_t)b * NBINS + kout) * FRAMES) * 2 + comp;

#pragma unroll
        for (int h = 0; h < 2; h++) {
            float v0, v1;
            asm("mov.b64 {%0,%1}, %2;" : "=f"(v0), "=f"(v1) : "l"(acc[j][h]));
            const int fA = f0 + m0 + 2 * h;
            if (fA < FRAMES)     out[base + (size_t)fA * 2]       = v0;
            if (fA + 1 < FRAMES) out[base + (size_t)(fA + 1) * 2] = v1;
        }
    }
}

extern "C" void kernel_launch(void* const* d_in, const int* in_sizes, int n_in,
                              void* d_out, int out_size)
{
    const float* x     = (const float*)d_in[0];
    const float* basis = (const float*)d_in[1];
    float* out         = (float*)d_out;

    dim3 grid((FRAMES + BM - 1) / BM,        // 8
              (BINS_TOT + BN - 1) / BN,      // 17
              32);                           // batch
    stft_gemm_kernel<<<grid, 256>>>(x, basis, out);
}

// round 2
// speedup vs baseline: 1.2613x; 1.2613x over previous
#include <cuda_runtime.h>

// ConvSTFT as 32 batched GEMMs: C[f,kb] = sum_n framed[f,n] * basis[kb,n]
// framed[f,n] = x[f*320 + n - 512] (zero-padded), basis cols nonzero only in
// n in [112,912) -> K_eff = 800.

#define T_LEN      160000
#define FRAMES     501
#define NBINS      513
#define BINS_TOT   1026
#define NFFT       1024
#define HOP        320
#define N0         112
#define KTOT       800
#define BK         16
#define BM         128
#define BN         128
#define NT         (KTOT / BK)   // 50 k-tiles

__global__ __launch_bounds__(256, 2)
void stft_gemm_kernel(const float* __restrict__ x,
                      const float* __restrict__ basis,
                      float* __restrict__ out)
{
    __shared__ __align__(16) float As[BK][BM + 4];   // [n][frame]
    __shared__ __align__(16) float Bs[BK][BN + 4];   // [n][bin]

    const int tid = threadIdx.x;
    const int f0  = blockIdx.x * BM;
    const int k0  = blockIdx.y * BN;
    const int b   = blockIdx.z;

    // Loader mapping: 16 consecutive n-columns per 16-thread group -> coalesced
    const int colL = tid & 15;
    const int rowL = tid >> 4;

    // Compute mapping: 8x8 tile, split as {4tx..4tx+3} U {64+4tx..} in M,
    // {4ty..4ty+3} U {64+4ty..} in N  -> conflict-free LDS.128
    const int tx = tid & 15;
    const int ty = tid >> 4;
    const int mA = tx * 4;
    const int nA = ty * 4;

    const float* xb = x + (size_t)b * T_LEN;

    float aR[8], bR[8];
    auto loadT = [&](int t) {
        const int kk = N0 + t * BK + colL;
#pragma unroll
        for (int i = 0; i < 8; i++) {
            const int m  = rowL + 16 * i;
            const int xi = (f0 + m) * HOP + kk - 512;
            aR[i] = (xi >= 0 && xi < T_LEN) ? xb[xi] : 0.0f;
            const int kb = k0 + m;
            bR[i] = (kb < BINS_TOT) ? basis[(size_t)kb * NFFT + kk] : 0.0f;
        }
    };

    // 64 fp32 accumulators as 32 packed f32x2 (pairs of adjacent frames)
    unsigned long long acc[4][8];
#pragma unroll
    for (int mi = 0; mi < 4; mi++)
#pragma unroll
        for (int j = 0; j < 8; j++) acc[mi][j] = 0ULL;

    loadT(0);

    for (int t = 0; t < NT; t++) {
        __syncthreads();
#pragma unroll
        for (int i = 0; i < 8; i++) {
            const int m = rowL + 16 * i;
            As[colL][m] = aR[i];
            Bs[colL][m] = bR[i];
        }
        __syncthreads();

        if (t + 1 < NT) loadT(t + 1);   // prefetch next tile into registers

#pragma unroll
        for (int k = 0; k < BK; k++) {
            // A fragments as aligned 64-bit pairs (free f32x2 packing)
            const ulonglong2 a01 = *(const ulonglong2*)&As[k][mA];
            const ulonglong2 a23 = *(const ulonglong2*)&As[k][mA + 64];
            unsigned long long ap[4] = { a01.x, a01.y, a23.x, a23.y };

            const float4 b0 = *(const float4*)&Bs[k][nA];
            const float4 b1 = *(const float4*)&Bs[k][nA + 64];
            const float bs[8] = { b0.x, b0.y, b0.z, b0.w,
                                  b1.x, b1.y, b1.z, b1.w };

#pragma unroll
            for (int j = 0; j < 8; j++) {
                unsigned long long bb;
                asm("mov.b64 %0, {%1,%1};" : "=l"(bb) : "f"(bs[j]));
#pragma unroll
                for (int mi = 0; mi < 4; mi++)
                    asm("fma.rn.f32x2 %0, %1, %2, %0;"
                        : "+l"(acc[mi][j]) : "l"(ap[mi]), "l"(bb));
            }
        }
    }

    // Epilogue: out[b, k, f, comp], comp stride 1, f stride 2
#pragma unroll
    for (int j = 0; j < 8; j++) {
        const int kb = k0 + nA + ((j < 4) ? j : 60 + j);  // nA+j or nA+64+(j-4)
        if (kb >= BINS_TOT) continue;
        int kout, comp;
        if (kb < NBINS) { kout = kb;         comp = 0; }
        else            { kout = kb - NBINS; comp = 1; }
        const size_t base = (((size_t)b * NBINS + kout) * FRAMES) * 2 + comp;

#pragma unroll
        for (int mi = 0; mi < 4; mi++) {
            float v0, v1;
            asm("mov.b64 {%0,%1}, %2;" : "=f"(v0), "=f"(v1) : "l"(acc[mi][j]));
            const int fA = f0 + ((mi < 2) ? (mA + 2 * mi) : (mA + 64 + 2 * (mi - 2)));
            if (fA < FRAMES)     out[base + (size_t)fA * 2]       = v0;
            if (fA + 1 < FRAMES) out[base + (size_t)(fA + 1) * 2] = v1;
        }
    }
}

extern "C" void kernel_launch(void* const* d_in, const int* in_sizes, int n_in,
                              void* d_out, int out_size)
{
    const float* x     = (const float*)d_in[0];
    const float* basis = (const float*)d_in[1];
    float* out         = (float*)d_out;

    dim3 grid((FRAMES + BM - 1) / BM,        // 4
              (BINS_TOT + BN - 1) / BN,      // 9
              32);                           // batch
    stft_gemm_kernel<<<grid, 256>>>(x, basis, out);
}

// round 4
// speedup vs baseline: 2.3165x; 1.8366x over previous
#include <cuda_runtime.h>
#include <cuda_bf16.h>
#include <cstdint>

// ConvSTFT via HMMA (mma.sync bf16) split-precision GEMM.
// C[f,q] = sum_n framed[f,n] * basisI[q,n]  per batch b
//   framed[f,n] = x[b, f*320 + n - 512]  (zero outside [0,160000))
//   basisI[q,n] = basis[(q>>1) + (q&1)*513, n]  (interleaved real/imag)
// Nonzero basis cols: n in [112,912) -> 13 chunks of 64 starting at 112.
// fp32 split: v = hi(bf16) + lo(bf16); C = Ah*Bh + Ah*Bl + Al*Bh  (3 passes).

#define TLEN    160000
#define NBATCH  32
#define FRAMES  501
#define NBINS   513
#define NFFT    1024
#define HOP     320
#define N0      112
#define NCH     13
#define TOTCH   (3 * NCH)      // 39 (chunk, pass) iterations
#define BM      128
#define BN      128

#define STAGE_BYTES 32768      // A tile 16KB + B tile 16KB
#define SMEM_TOTAL  65536      // 2 stages; reused as 128x128 fp32 out tile

// ---- scratch (device globals) ----
__device__ __align__(16) __nv_bfloat16 g_x_hi[(size_t)NBATCH * TLEN];
__device__ __align__(16) __nv_bfloat16 g_x_lo[(size_t)NBATCH * TLEN];
__device__ __align__(16) __nv_bfloat16 g_b_hi[(size_t)2 * NBINS * NFFT];
__device__ __align__(16) __nv_bfloat16 g_b_lo[(size_t)2 * NBINS * NFFT];

__device__ __forceinline__ uint32_t smem_u32(const void* p) {
    uint32_t a;
    asm("{ .reg .u64 t; cvta.to.shared.u64 t, %1; cvt.u32.u64 %0, t; }" : "=r"(a) : "l"(p));
    return a;
}
__device__ __forceinline__ uint32_t swz(uint32_t off) {   // SW128 xor swizzle
    return off ^ ((off >> 3) & 0x70);
}
__device__ __forceinline__ void cp16(uint32_t dst, const void* src, uint32_t sz) {
    asm volatile("cp.async.cg.shared.global [%0], [%1], 16, %2;"
                 :: "r"(dst), "l"(src), "r"(sz));
}
#define CP_COMMIT() asm volatile("cp.async.commit_group;" ::: "memory")
#define CP_WAIT1()  asm volatile("cp.async.wait_group 1;" ::: "memory")

__device__ __forceinline__ void ldmx4(uint32_t* r, uint32_t addr) {
    asm volatile("ldmatrix.sync.aligned.m8n8.x4.shared.b16 {%0,%1,%2,%3}, [%4];"
                 : "=r"(r[0]), "=r"(r[1]), "=r"(r[2]), "=r"(r[3]) : "r"(addr));
}
__device__ __forceinline__ void mma16816(float* c, const uint32_t* a, const uint32_t* b) {
    asm volatile("mma.sync.aligned.m16n8k16.row.col.f32.bf16.bf16.f32 "
                 "{%0,%1,%2,%3}, {%4,%5,%6,%7}, {%8,%9}, {%0,%1,%2,%3};"
                 : "+f"(c[0]), "+f"(c[1]), "+f"(c[2]), "+f"(c[3])
                 : "r"(a[0]), "r"(a[1]), "r"(a[2]), "r"(a[3]), "r"(b[0]), "r"(b[1]));
}

// ---- pre-pass: fp32 -> (hi, lo) bf16 ----
__global__ void convert_kernel(const float* __restrict__ x,
                               const float* __restrict__ basis) {
    const size_t NX = (size_t)NBATCH * TLEN;
    const size_t NB = (size_t)2 * NBINS * NFFT;
    size_t idx = (size_t)blockIdx.x * blockDim.x + threadIdx.x;
    if (idx >= NX + NB) return;
    float v = (idx < NX) ? x[idx] : basis[idx - NX];
    __nv_bfloat16 h = __float2bfloat16(v);
    __nv_bfloat16 l = __float2bfloat16(v - __bfloat162float(h));
    if (idx < NX) { g_x_hi[idx] = h; g_x_lo[idx] = l; }
    else          { g_b_hi[idx - NX] = h; g_b_lo[idx - NX] = l; }
}

__global__ __launch_bounds__(256, 1)
void stft_hmma_kernel(float* __restrict__ out) {
    extern __shared__ __align__(16) char sm[];
    const uint32_t smb = smem_u32(sm);

    const int tid  = threadIdx.x;
    const int lane = tid & 31;
    const int wid  = tid >> 5;
    const int wm   = wid >> 2;          // warp M group (0-1): 64 frames
    const int wn   = wid & 3;           // warp N group (0-3): 32 bins

    const int f0 = blockIdx.x * BM;
    const int k0 = blockIdx.y * BN;
    const int b  = blockIdx.z;

    // ldmatrix lane address components
    const int aRow = wm * 64 + (lane & 15);
    const int aCol = ((lane >> 4) & 1) * 16;
    const int bRow = wn * 32 + (lane & 7) + ((lane >> 4) & 1) * 8;
    const int bCol = ((lane >> 3) & 1) * 16;

    float acc[4][4][4];
#pragma unroll
    for (int mi = 0; mi < 4; mi++)
#pragma unroll
        for (int ni = 0; ni < 4; ni++)
#pragma unroll
            for (int e = 0; e < 4; e++) acc[mi][ni][e] = 0.f;

    const size_t xb = (size_t)b * TLEN;

    // ---- chunk loader: (chunk cc, pass p) -> stage s ----
    auto load_chunk = [&](int c, int s) {
        const int p  = c / NCH;
        const int cc = c - p * NCH;
        const int kcol = N0 + cc * 64;
        const __nv_bfloat16* xsel = (p == 2) ? g_x_lo : g_x_hi;
        const __nv_bfloat16* bsel = (p == 1) ? g_b_lo : g_b_hi;
        const uint32_t stA = smb + s * STAGE_BYTES;
        const uint32_t stB = stA + 16384;
#pragma unroll
        for (int i = 0; i < 4; i++) {
            const int idx = tid + 256 * i;     // 0..1023
            const int r = idx >> 3;            // row 0..127
            const int u = idx & 7;             // 16B unit 0..7
            const uint32_t off = swz((uint32_t)(r * 128 + u * 16));
            // A (frames)
            const int xi0 = (f0 + r) * HOP + kcol + u * 8 - 512;
            const uint32_t szA = (xi0 >= 0 && xi0 + 8 <= TLEN) ? 16u : 0u;
            cp16(stA + off, xsel + xb + (xi0 < 0 ? 0 : xi0), szA);
            // B (interleaved bins)
            const int q = k0 + r;
            const int rowb = (q >> 1) + (q & 1) * NBINS;
            const uint32_t szB = (q < 2 * NBINS) ? 16u : 0u;
            cp16(stB + off, bsel + (size_t)(q < 2 * NBINS ? rowb : 0) * NFFT
                                 + kcol + u * 8, szB);
        }
        CP_COMMIT();
    };

    load_chunk(0, 0);
    load_chunk(1, 1);

    for (int c = 0; c < TOTCH; c++) {
        CP_WAIT1();
        __syncthreads();

        const uint32_t stA = smb + (c & 1) * STAGE_BYTES;
        const uint32_t stB = stA + 16384;

#pragma unroll
        for (int ks = 0; ks < 4; ks++) {
            uint32_t afr[4][4];
#pragma unroll
            for (int mi = 0; mi < 4; mi++)
                ldmx4(afr[mi], stA + swz((uint32_t)((aRow + mi * 16) * 128
                                                    + ks * 32 + aCol)));
            uint32_t bfr[4][2];
#pragma unroll
            for (int np = 0; np < 2; np++) {
                uint32_t r4[4];
                ldmx4(r4, stB + swz((uint32_t)((bRow + np * 16) * 128
                                               + ks * 32 + bCol)));
                bfr[np * 2][0]     = r4[0]; bfr[np * 2][1]     = r4[1];
                bfr[np * 2 + 1][0] = r4[2]; bfr[np * 2 + 1][1] = r4[3];
            }
#pragma unroll
            for (int mi = 0; mi < 4; mi++)
#pragma unroll
                for (int ni = 0; ni < 4; ni++)
                    mma16816(acc[mi][ni], afr[mi], bfr[ni]);
        }

        __syncthreads();
        if (c + 2 < TOTCH) load_chunk(c + 2, c & 1);
    }

    // ---- epilogue: stage fp32 tile [q][f] in smem, then coalesced float2 out ----
    __syncthreads();
    float* ot = (float*)sm;       // 128 q rows x 128 f cols = 64KB
#pragma unroll
    for (int mi = 0; mi < 4; mi++)
#pragma unroll
        for (int ni = 0; ni < 4; ni++) {
            const int row = wm * 64 + mi * 16 + (lane >> 2);
            const int col = wn * 32 + ni * 8 + (lane & 3) * 2;
            ot[col * 128 + row]           = acc[mi][ni][0];
            ot[(col + 1) * 128 + row]     = acc[mi][ni][1];
            ot[col * 128 + row + 8]       = acc[mi][ni][2];
            ot[(col + 1) * 128 + row + 8] = acc[mi][ni][3];
        }
    __syncthreads();

#pragma unroll
    for (int i = 0; i < 32; i++) {
        const int idx = tid + 256 * i;   // 0..8191
        const int j = idx >> 7;          // bin pair 0..63
        const int f = idx & 127;
        const int q = k0 + 2 * j;
        const int ff = f0 + f;
        if (q < 2 * NBINS && ff < FRAMES) {
            const int kout = q >> 1;
            float2 v;
            v.x = ot[(2 * j) * 128 + f];
            v.y = ot[(2 * j + 1) * 128 + f];
            *(float2*)(out + (((size_t)b * NBINS + kout) * FRAMES + ff) * 2) = v;
        }
    }
}

extern "C" void kernel_launch(void* const* d_in, const int* in_sizes, int n_in,
                              void* d_out, int out_size) {
    const float* x     = (const float*)d_in[0];
    const float* basis = (const float*)d_in[1];
    float* out         = (float*)d_out;

    const size_t total = (size_t)NBATCH * TLEN + (size_t)2 * NBINS * NFFT;
    convert_kernel<<<(unsigned)((total + 255) / 256), 256>>>(x, basis);

    cudaFuncSetAttribute(stft_hmma_kernel,
                         cudaFuncAttributeMaxDynamicSharedMemorySize, SMEM_TOTAL);
    dim3 grid((FRAMES + BM - 1) / BM,          // 4
              (2 * NBINS + BN - 1) / BN,       // 9
              NBATCH);                         // 32
    stft_hmma_kernel<<<grid, 256, SMEM_TOTAL>>>(out);
}